// round 1
// baseline (speedup 1.0000x reference)
#include <cuda_runtime.h>
#include <cstdint>

#define VN 128
#define TT 5
#define NTHREADS 256

// ---------------------------------------------------------------------------
// Precomputed collapsed-weight constants (entire linear network folds into
// per-node scalar projections + adjacency chain weights).
// out[b] = sum_j ( r2[j]*p[j] + r3[j]*q[j] ) + cond[b].ac + K
//   p[j] = nodes[b,j,:5].gn1 + node_params[b,j,:8].d1 + k1
//   q[j] = nodes[b,j,:5].gn2 + node_params[b,j,:8].d2 + k2
//   r1 = P^T 1 / V,  r2 = P^T r1,  r3 = P^T r2,  P = diag(1/deg) Asum
// ---------------------------------------------------------------------------
struct Pre {
    float gn1[5], gn2[5];
    float d1[8], d2[8];
    float ac[10];
    float k1, k2, K;
};
__device__ Pre g_pre;

// out[k] = sum_m W[k*M+m] * v[m]; warp-per-row, coalesced global reads of W.
__device__ __forceinline__ void mv(const float* __restrict__ W, const float* v,
                                   float* out, int K, int M) {
    int tid  = threadIdx.x;
    int wid  = tid >> 5;
    int lane = tid & 31;
    for (int k = wid; k < K; k += 8) {
        float acc = 0.f;
        for (int m = lane; m < M; m += 32)
            acc += W[k * M + m] * v[m];
        #pragma unroll
        for (int o = 16; o; o >>= 1) acc += __shfl_xor_sync(0xffffffffu, acc, o);
        if (lane == 0) out[k] = acc;
    }
}

// block-wide dot of a (global) with b (smem/any), n <= a few hundred
__device__ float blk_dot(const float* __restrict__ a, const float* b, int n,
                         float* red) {
    int tid = threadIdx.x;
    float acc = 0.f;
    for (int i = tid; i < n; i += NTHREADS) acc += a[i] * b[i];
    red[tid] = acc;
    __syncthreads();
    for (int s = NTHREADS / 2; s; s >>= 1) {
        if (tid < s) red[tid] += red[tid + s];
        __syncthreads();
    }
    float r = red[0];
    __syncthreads();
    return r;
}

__global__ void precompute_kernel(
    const float* __restrict__ w_ne0, const float* __restrict__ b_ne0,
    const float* __restrict__ w_ne1, const float* __restrict__ b_ne1,
    const float* __restrict__ w_g1,  const float* __restrict__ b_g1,
    const float* __restrict__ w_g2,  const float* __restrict__ b_g2,
    const float* __restrict__ w_g3a, const float* __restrict__ b_g3a,
    const float* __restrict__ w_g3b, const float* __restrict__ b_g3b,
    const float* __restrict__ w_ce0, const float* __restrict__ b_ce0,
    const float* __restrict__ w_ce1, const float* __restrict__ b_ce1,
    const float* __restrict__ w_f0,  const float* __restrict__ b_f0,
    const float* __restrict__ w_f1,  const float* __restrict__ b_f1,
    const float* __restrict__ w_f2,  const float* __restrict__ b_f2,
    const float* __restrict__ w_f3,  const float* __restrict__ b_f3)
{
    __shared__ float v3[32], v2[64], v1[128], wfv[144], t16[32];
    __shared__ float evec[256], fvec[128], tmp64[64];
    __shared__ float a1[32], a2[32], g1a[37], g1b[37], ng1[64], ng2[64];
    __shared__ float d1v[8], d2v[8], acv[10], red[NTHREADS];
    int tid = threadIdx.x;

    // fc head collapse: Wf = Wf0 Wf1 Wf2 Wf3  (144x1)
    if (tid < 32) v3[tid] = w_f3[tid];
    __syncthreads();
    mv(w_f2, v3, v2, 64, 32);
    __syncthreads();
    mv(w_f1, v2, v1, 128, 64);
    __syncthreads();
    mv(w_f0, v1, wfv, 144, 128);    // wfv[0:128]=Wfg, wfv[128:144]=Wfc
    __syncthreads();

    // cond branch: ac = Wce0 (Wce1 Wfc)
    mv(w_ce1, wfv + 128, t16, 32, 16);
    // g3 branch: e = W3b Wfg ; f = W3a e
    mv(w_g3b, wfv, evec, 256, 128);
    __syncthreads();
    mv(w_ce0, t16, acv, 10, 32);
    mv(w_g3a, evec, fvec, 128, 256);
    __syncthreads();
    if (tid < 64) tmp64[tid] = fvec[tid] + fvec[64 + tid];
    __syncthreads();
    // alpha1 = W2 (ft+fb), alpha2 = -W2 fb
    mv(w_g2, tmp64, a1, 32, 64);
    mv(w_g2, fvec + 64, a2, 32, 64);
    __syncthreads();
    if (tid < 32) a2[tid] = -a2[tid];
    __syncthreads();
    // fold through g1
    mv(w_g1, a1, g1a, 37, 32);
    mv(w_g1, a2, g1b, 37, 32);
    __syncthreads();
    // fold through node encoder
    mv(w_ne1, g1a + 5, ng1, 64, 32);
    mv(w_ne1, g1b + 5, ng2, 64, 32);
    __syncthreads();
    mv(w_ne0, ng1, d1v, 8, 64);
    mv(w_ne0, ng2, d2v, 8, 64);
    __syncthreads();

    // scalar bias folds
    float bf = blk_dot(b_f2, v3, 32, red) + blk_dot(b_f1, v2, 64, red)
             + blk_dot(b_f0, v1, 128, red);
    float kc = blk_dot(b_ce0, t16, 32, red) + blk_dot(b_ce1, wfv + 128, 16, red);
    float k3 = blk_dot(b_g2, fvec, 64, red) + blk_dot(b_g3a, evec, 256, red)
             + blk_dot(b_g3b, wfv, 128, red);
    float k1 = blk_dot(b_g1, a1, 32, red) + blk_dot(b_ne0, ng1, 64, red)
             + blk_dot(b_ne1, g1a + 5, 32, red);
    float k2 = blk_dot(b_g1, a2, 32, red) + blk_dot(b_ne0, ng2, 64, red)
             + blk_dot(b_ne1, g1b + 5, 32, red);

    if (tid < 5)  { g_pre.gn1[tid] = g1a[tid]; g_pre.gn2[tid] = g1b[tid]; }
    if (tid < 8)  { g_pre.d1[tid]  = d1v[tid]; g_pre.d2[tid]  = d2v[tid]; }
    if (tid < 10) g_pre.ac[tid] = acv[tid];
    if (tid == 0) {
        g_pre.k1 = k1;
        g_pre.k2 = k2;
        g_pre.K  = k3 + kc + bf + b_f3[0];
    }
}

// ---------------------------------------------------------------------------
// Main kernel: one block per batch. Streams 320KB of edges via f4 staging,
// builds Asum (128x128) in SMEM, runs r1->r2->r3 matvec chain, then the
// per-node scalar dots + block reduction.
// ---------------------------------------------------------------------------
// smem layout (floats): Asum 16384 | stage 5120 | deg 128 | w0 128 | rA 128
//                       | rB 128 | red 256  -> 22272 floats = 89088 B
#define SMEM_FLOATS (16384 + 5120 + 128 + 128 + 128 + 128 + 256)
#define SMEM_BYTES  (SMEM_FLOATS * 4)

__global__ __launch_bounds__(NTHREADS, 2) void gnn_main(
    const float* __restrict__ edges,
    const float* __restrict__ nodes,
    const float* __restrict__ nparams,
    const float* __restrict__ cond,
    float* __restrict__ out)
{
    extern __shared__ float sm[];
    float* Asum  = sm;             // 16384
    float* stage = Asum + 16384;   // 5120 (8 rows x 640)
    float* deg   = stage + 5120;   // 128
    float* w0    = deg + 128;      // 128
    float* rA    = w0 + 128;       // 128
    float* rB    = rA + 128;       // 128
    float* red   = rB + 128;       // 256

    const int b   = blockIdx.x;
    const int tid = threadIdx.x;
    const int wid = tid >> 5, lane = tid & 31;

    // ---- Phase 1: Asum[i][j] = sum_{t=1..4} edges[b,i,j,t] ----
    const float4* src = (const float4*)(edges + (size_t)b * VN * VN * TT);
    float4* st4 = (float4*)stage;
    for (int ch = 0; ch < 16; ch++) {
        const float4* s4 = src + ch * 1280;   // 8 rows * 160 f4
        #pragma unroll
        for (int k = 0; k < 5; k++)
            st4[tid + NTHREADS * k] = s4[tid + NTHREADS * k];
        __syncthreads();
        #pragma unroll
        for (int k = 0; k < 4; k++) {
            int idx = tid + NTHREADS * k;     // 0..1023
            int ri  = idx >> 7;
            int j   = idx & 127;
            const float* s = stage + ri * 640 + 5 * j;
            Asum[(ch * 8 + ri) * VN + j] = s[1] + s[2] + s[3] + s[4];
        }
        __syncthreads();
    }

    // ---- deg[i] = sum_j Asum[i][j]; w0 = 1/(V*deg) ----
    for (int i = wid; i < VN; i += 8) {
        float acc = 0.f;
        #pragma unroll
        for (int u = 0; u < 4; u++) acc += Asum[i * VN + lane + 32 * u];
        #pragma unroll
        for (int o = 16; o; o >>= 1) acc += __shfl_xor_sync(0xffffffffu, acc, o);
        if (lane == 0) {
            float d = fmaxf(acc, 1e-8f);
            deg[i] = d;
            w0[i]  = 1.f / (d * (float)VN);
        }
    }
    __syncthreads();

    // ---- r1 = Asum^T w0 ----
    if (tid < VN) {
        float acc = 0.f;
        #pragma unroll 8
        for (int i = 0; i < VN; i++) acc += Asum[i * VN + tid] * w0[i];
        rA[tid] = acc;                       // r1
    }
    __syncthreads();
    if (tid < VN) w0[tid] = rA[tid] / deg[tid];
    __syncthreads();
    if (tid < VN) {
        float acc = 0.f;
        #pragma unroll 8
        for (int i = 0; i < VN; i++) acc += Asum[i * VN + tid] * w0[i];
        rA[tid] = acc;                       // r2
    }
    __syncthreads();
    if (tid < VN) w0[tid] = rA[tid] / deg[tid];
    __syncthreads();
    if (tid < VN) {
        float acc = 0.f;
        #pragma unroll 8
        for (int i = 0; i < VN; i++) acc += Asum[i * VN + tid] * w0[i];
        rB[tid] = acc;                       // r3
    }
    __syncthreads();

    // ---- per-node scalars + reduction ----
    float part = 0.f;
    if (tid < VN) {
        const int j = tid;
        const float* nd = nodes   + ((size_t)b * VN + j) * 5;
        const float* np = nparams + ((size_t)b * VN + j) * 8;
        float p = g_pre.k1, q = g_pre.k2;
        #pragma unroll
        for (int m = 0; m < 5; m++) {
            float x = nd[m];
            p += x * g_pre.gn1[m];
            q += x * g_pre.gn2[m];
        }
        #pragma unroll
        for (int m = 0; m < 8; m++) {
            float x = np[m];
            p += x * g_pre.d1[m];
            q += x * g_pre.d2[m];
        }
        part = rA[j] * p + rB[j] * q;
    }
    red[tid] = part;
    __syncthreads();
    for (int s = NTHREADS / 2; s; s >>= 1) {
        if (tid < s) red[tid] += red[tid + s];
        __syncthreads();
    }
    if (tid == 0) {
        float acc = red[0] + g_pre.K;
        const float* c = cond + (size_t)b * 10;
        #pragma unroll
        for (int m = 0; m < 10; m++) acc += c[m] * g_pre.ac[m];
        out[b] = acc;
    }
}

extern "C" void kernel_launch(void* const* d_in, const int* in_sizes, int n_in,
                              void* d_out, int out_size) {
    const float* edges   = (const float*)d_in[0];
    const float* nodes   = (const float*)d_in[1];
    const float* nparams = (const float*)d_in[2];
    const float* cond    = (const float*)d_in[3];

    cudaFuncSetAttribute(gnn_main, cudaFuncAttributeMaxDynamicSharedMemorySize,
                         SMEM_BYTES);

    precompute_kernel<<<1, NTHREADS>>>(
        (const float*)d_in[4],  (const float*)d_in[5],
        (const float*)d_in[6],  (const float*)d_in[7],
        (const float*)d_in[8],  (const float*)d_in[9],
        (const float*)d_in[10], (const float*)d_in[11],
        (const float*)d_in[12], (const float*)d_in[13],
        (const float*)d_in[14], (const float*)d_in[15],
        (const float*)d_in[16], (const float*)d_in[17],
        (const float*)d_in[18], (const float*)d_in[19],
        (const float*)d_in[20], (const float*)d_in[21],
        (const float*)d_in[22], (const float*)d_in[23],
        (const float*)d_in[24], (const float*)d_in[25],
        (const float*)d_in[26], (const float*)d_in[27]);

    gnn_main<<<512, NTHREADS, SMEM_BYTES>>>(edges, nodes, nparams, cond,
                                            (float*)d_out);
}

// round 2
// speedup vs baseline: 1.2526x; 1.2526x over previous
#include <cuda_runtime.h>
#include <cstdint>

#define VN 128
#define TT 5
#define NTHREADS 256

// ---------------------------------------------------------------------------
// Collapsed-weight constants + per-batch weight-independent sums.
// out[b] = gn1.S2n + d1.S2p + k1*S2s + gn2.S3n + d2.S3p + k2*S3s + ac.cond + K
// where S2n[m] = sum_j r2[j]*nodes[b,j,m], etc.
// ---------------------------------------------------------------------------
struct Pre {
    float gn1[5], gn2[5];
    float d1[8], d2[8];
    float ac[10];
    float k1, k2, K;
};
__device__ Pre g_pre;
__device__ float g_sums[512 * 28];

// ---------------- cp.async helpers ----------------
__device__ __forceinline__ void cp16(uint32_t s, const void* g) {
    asm volatile("cp.async.cg.shared.global [%0], [%1], 16;\n" :: "r"(s), "l"(g));
}
__device__ __forceinline__ void cp_commit() {
    asm volatile("cp.async.commit_group;\n" ::: "memory");
}
template <int N>
__device__ __forceinline__ void cp_wait() {
    asm volatile("cp.async.wait_group %0;\n" :: "n"(N) : "memory");
}

// out[k] = sum_m W[k*M+m] * v[m]; warp-per-row.
__device__ __forceinline__ void mv(const float* __restrict__ W, const float* v,
                                   float* out, int K, int M) {
    int tid  = threadIdx.x;
    int wid  = tid >> 5;
    int lane = tid & 31;
    for (int k = wid; k < K; k += 8) {
        float acc = 0.f;
        for (int m = lane; m < M; m += 32)
            acc += W[k * M + m] * v[m];
        #pragma unroll
        for (int o = 16; o; o >>= 1) acc += __shfl_xor_sync(0xffffffffu, acc, o);
        if (lane == 0) out[k] = acc;
    }
}

__device__ __forceinline__ float warp_dot(const float* __restrict__ a,
                                          const float* b, int n, int lane) {
    float acc = 0.f;
    for (int i = lane; i < n; i += 32) acc += a[i] * b[i];
    #pragma unroll
    for (int o = 16; o; o >>= 1) acc += __shfl_xor_sync(0xffffffffu, acc, o);
    return acc;
}

// ---------------------------------------------------------------------------
// Weight collapse (runs as block 0, concurrent with batch blocks).
// ~12 dependent phases; all bias dots batched into one parallel phase.
// ---------------------------------------------------------------------------
__device__ void precompute_body(
    float* sm,
    const float* __restrict__ w_ne0, const float* __restrict__ b_ne0,
    const float* __restrict__ w_ne1, const float* __restrict__ b_ne1,
    const float* __restrict__ w_g1,  const float* __restrict__ b_g1,
    const float* __restrict__ w_g2,  const float* __restrict__ b_g2,
    const float* __restrict__ w_g3a, const float* __restrict__ b_g3a,
    const float* __restrict__ w_g3b, const float* __restrict__ b_g3b,
    const float* __restrict__ w_ce0, const float* __restrict__ b_ce0,
    const float* __restrict__ w_ce1, const float* __restrict__ b_ce1,
    const float* __restrict__ w_f0,  const float* __restrict__ b_f0,
    const float* __restrict__ w_f1,  const float* __restrict__ b_f1,
    const float* __restrict__ w_f2,  const float* __restrict__ b_f2,
    const float* __restrict__ w_f3,  const float* __restrict__ b_f3)
{
    float* v3   = sm;          // 32
    float* v2   = v3 + 32;     // 64
    float* v1   = v2 + 64;     // 128
    float* wfv  = v1 + 128;    // 144 (pad 160)
    float* t16  = wfv + 160;   // 32
    float* evec = t16 + 32;    // 256
    float* fvec = evec + 256;  // 128
    float* tmp64= fvec + 128;  // 64
    float* a1   = tmp64 + 64;  // 32
    float* a2   = a1 + 32;     // 32
    float* g1a  = a2 + 32;     // 40
    float* g1b  = g1a + 40;    // 40
    float* ng1  = g1b + 40;    // 64
    float* ng2  = ng1 + 64;    // 64
    float* d1v  = ng2 + 64;    // 8
    float* d2v  = d1v + 8;     // 8
    float* acv  = d2v + 8;     // 12
    float* kres = acv + 12;    // 16

    int tid = threadIdx.x, wid = tid >> 5, lane = tid & 31;

    if (tid < 32) v3[tid] = w_f3[tid];
    __syncthreads();
    mv(w_f2, v3, v2, 64, 32);
    __syncthreads();
    mv(w_f1, v2, v1, 128, 64);
    __syncthreads();
    mv(w_f0, v1, wfv, 144, 128);         // [0:128]=Wfg, [128:144]=Wfc
    __syncthreads();
    mv(w_g3b, wfv, evec, 256, 128);
    mv(w_ce1, wfv + 128, t16, 32, 16);
    __syncthreads();
    mv(w_g3a, evec, fvec, 128, 256);
    mv(w_ce0, t16, acv, 10, 32);
    __syncthreads();
    if (tid < 64) tmp64[tid] = fvec[tid] + fvec[64 + tid];
    __syncthreads();
    mv(w_g2, tmp64, a1, 32, 64);
    mv(w_g2, fvec + 64, a2, 32, 64);
    __syncthreads();
    if (tid < 32) a2[tid] = -a2[tid];
    __syncthreads();
    mv(w_g1, a1, g1a, 37, 32);
    mv(w_g1, a2, g1b, 37, 32);
    __syncthreads();
    mv(w_ne1, g1a + 5, ng1, 64, 32);
    mv(w_ne1, g1b + 5, ng2, 64, 32);
    __syncthreads();
    mv(w_ne0, ng1, d1v, 8, 64);
    mv(w_ne0, ng2, d2v, 8, 64);
    __syncthreads();

    // one parallel bias-dot phase: 14 dots across 8 warps
    for (int o = wid; o < 14; o += 8) {
        float r;
        switch (o) {
            case 0:  r = warp_dot(b_f2, v3, 32, lane); break;
            case 1:  r = warp_dot(b_f1, v2, 64, lane); break;
            case 2:  r = warp_dot(b_f0, v1, 128, lane); break;
            case 3:  r = warp_dot(b_ce0, t16, 32, lane); break;
            case 4:  r = warp_dot(b_ce1, wfv + 128, 16, lane); break;
            case 5:  r = warp_dot(b_g2, fvec, 64, lane); break;
            case 6:  r = warp_dot(b_g3a, evec, 256, lane); break;
            case 7:  r = warp_dot(b_g3b, wfv, 128, lane); break;
            case 8:  r = warp_dot(b_g1, a1, 32, lane); break;
            case 9:  r = warp_dot(b_ne0, ng1, 64, lane); break;
            case 10: r = warp_dot(b_ne1, g1a + 5, 32, lane); break;
            case 11: r = warp_dot(b_g1, a2, 32, lane); break;
            case 12: r = warp_dot(b_ne0, ng2, 64, lane); break;
            default: r = warp_dot(b_ne1, g1b + 5, 32, lane); break;
        }
        if (lane == 0) kres[o] = r;
    }
    __syncthreads();

    if (tid < 5)  { g_pre.gn1[tid] = g1a[tid]; g_pre.gn2[tid] = g1b[tid]; }
    if (tid < 8)  { g_pre.d1[tid]  = d1v[tid]; g_pre.d2[tid]  = d2v[tid]; }
    if (tid < 10) g_pre.ac[tid] = acv[tid];
    if (tid == 0) {
        g_pre.k1 = kres[8] + kres[9] + kres[10];
        g_pre.k2 = kres[11] + kres[12] + kres[13];
        g_pre.K  = kres[0] + kres[1] + kres[2] + kres[3] + kres[4]
                 + kres[5] + kres[6] + kres[7] + b_f3[0];
    }
}

// ---------------------------------------------------------------------------
// Fused main kernel. Block 0: weight collapse. Blocks 1..512: batch b-1.
// Edge streaming: 16 chunks x 20KB, double-buffered cp.async.cg.
// smem: Asum 16384 | stage 2x5120 | deg 128 | w0 128 | rA 128 | rB 128
// ---------------------------------------------------------------------------
#define SMEM_FLOATS (16384 + 10240 + 128 + 128 + 128 + 128)
#define SMEM_BYTES  (SMEM_FLOATS * 4)

__global__ __launch_bounds__(NTHREADS, 2) void gnn_fused(
    const float* __restrict__ edges,
    const float* __restrict__ nodes,
    const float* __restrict__ nparams,
    const float* w_ne0, const float* b_ne0, const float* w_ne1, const float* b_ne1,
    const float* w_g1,  const float* b_g1,  const float* w_g2,  const float* b_g2,
    const float* w_g3a, const float* b_g3a, const float* w_g3b, const float* b_g3b,
    const float* w_ce0, const float* b_ce0, const float* w_ce1, const float* b_ce1,
    const float* w_f0,  const float* b_f0,  const float* w_f1,  const float* b_f1,
    const float* w_f2,  const float* b_f2,  const float* w_f3,  const float* b_f3)
{
    extern __shared__ float sm[];
    const int tid = threadIdx.x;
    const int wid = tid >> 5, lane = tid & 31;

    if (blockIdx.x == 0) {
        precompute_body(sm, w_ne0, b_ne0, w_ne1, b_ne1, w_g1, b_g1, w_g2, b_g2,
                        w_g3a, b_g3a, w_g3b, b_g3b, w_ce0, b_ce0, w_ce1, b_ce1,
                        w_f0, b_f0, w_f1, b_f1, w_f2, b_f2, w_f3, b_f3);
        return;
    }
    const int b = blockIdx.x - 1;

    float* Asum  = sm;               // 16384
    float* stage = Asum + 16384;     // 2 x 5120
    float* deg   = stage + 10240;    // 128
    float* w0    = deg + 128;        // 128
    float* rA    = w0 + 128;         // 128
    float* rB    = rA + 128;         // 128

    const float4* src = (const float4*)(edges + (size_t)b * VN * VN * TT);
    uint32_t stage_s = (uint32_t)__cvta_generic_to_shared(stage);

    // issue chunk 0
    {
        const float4* s4 = src;
        #pragma unroll
        for (int k = 0; k < 5; k++)
            cp16(stage_s + (uint32_t)(tid + NTHREADS * k) * 16, s4 + tid + NTHREADS * k);
        cp_commit();
    }

    for (int ch = 0; ch < 16; ch++) {
        if (ch < 15) {
            const float4* s4 = src + (ch + 1) * 1280;
            uint32_t dst = stage_s + ((ch + 1) & 1) * 5120 * 4;
            #pragma unroll
            for (int k = 0; k < 5; k++)
                cp16(dst + (uint32_t)(tid + NTHREADS * k) * 16, s4 + tid + NTHREADS * k);
            cp_commit();
            cp_wait<1>();
        } else {
            cp_wait<0>();
        }
        __syncthreads();
        const float* sb = stage + (ch & 1) * 5120;
        #pragma unroll
        for (int k = 0; k < 4; k++) {
            int idx = tid + NTHREADS * k;        // 0..1023
            int ri  = idx >> 7;
            int j   = idx & 127;
            const float* s = sb + ri * 640 + 5 * j;
            Asum[(ch * 8 + ri) * VN + j] = s[1] + s[2] + s[3] + s[4];
        }
        __syncthreads();
    }

    // deg[i] = row sum; w0 = 1/(V*deg)
    for (int i = wid; i < VN; i += 8) {
        float acc = 0.f;
        #pragma unroll
        for (int u = 0; u < 4; u++) acc += Asum[i * VN + lane + 32 * u];
        #pragma unroll
        for (int o = 16; o; o >>= 1) acc += __shfl_xor_sync(0xffffffffu, acc, o);
        if (lane == 0) {
            float d = fmaxf(acc, 1e-8f);
            deg[i] = d;
            w0[i]  = 1.f / (d * (float)VN);
        }
    }
    __syncthreads();

    // r1 = Asum^T w0 ; r2 ; r3
    if (tid < VN) {
        float acc = 0.f;
        #pragma unroll 8
        for (int i = 0; i < VN; i++) acc += Asum[i * VN + tid] * w0[i];
        rA[tid] = acc;                       // r1
    }
    __syncthreads();
    if (tid < VN) w0[tid] = rA[tid] / deg[tid];
    __syncthreads();
    if (tid < VN) {
        float acc = 0.f;
        #pragma unroll 8
        for (int i = 0; i < VN; i++) acc += Asum[i * VN + tid] * w0[i];
        rA[tid] = acc;                       // r2
    }
    __syncthreads();
    if (tid < VN) w0[tid] = rA[tid] / deg[tid];
    __syncthreads();
    if (tid < VN) {
        float acc = 0.f;
        #pragma unroll 8
        for (int i = 0; i < VN; i++) acc += Asum[i * VN + tid] * w0[i];
        rB[tid] = acc;                       // r3
    }
    __syncthreads();

    // weight-independent per-batch sums: 28 outputs, 4 per warp (well, 3-4)
    // o in [0,13]: uses rA(r2); o in [14,27]: uses rB(r3).
    // m = o % 14: m<5 -> nodes[.,m]; m<13 -> params[.,m-5]; m==13 -> 1
    for (int o = wid; o < 28; o += 8) {
        const float* r = (o >= 14) ? rB : rA;
        int m = (o >= 14) ? o - 14 : o;
        float acc = 0.f;
        #pragma unroll 4
        for (int j = lane; j < VN; j += 32) {
            float x;
            if (m < 5)       x = nodes[((size_t)b * VN + j) * 5 + m];
            else if (m < 13) x = nparams[((size_t)b * VN + j) * 8 + (m - 5)];
            else             x = 1.f;
            acc += r[j] * x;
        }
        #pragma unroll
        for (int off = 16; off; off >>= 1)
            acc += __shfl_xor_sync(0xffffffffu, acc, off);
        if (lane == 0) g_sums[b * 28 + o] = acc;
    }
}

// ---------------------------------------------------------------------------
// Final combine: 512 outputs, 1 block.
// ---------------------------------------------------------------------------
__global__ void gnn_final(const float* __restrict__ cond, float* __restrict__ out) {
    int b = threadIdx.x;
    const float* S = g_sums + b * 28;
    float acc = g_pre.K + g_pre.k1 * S[13] + g_pre.k2 * S[27];
    #pragma unroll
    for (int m = 0; m < 5; m++)
        acc += g_pre.gn1[m] * S[m] + g_pre.gn2[m] * S[14 + m];
    #pragma unroll
    for (int m = 0; m < 8; m++)
        acc += g_pre.d1[m] * S[5 + m] + g_pre.d2[m] * S[19 + m];
    const float* c = cond + (size_t)b * 10;
    #pragma unroll
    for (int m = 0; m < 10; m++) acc += g_pre.ac[m] * c[m];
    out[b] = acc;
}

extern "C" void kernel_launch(void* const* d_in, const int* in_sizes, int n_in,
                              void* d_out, int out_size) {
    const float* edges   = (const float*)d_in[0];
    const float* nodes   = (const float*)d_in[1];
    const float* nparams = (const float*)d_in[2];
    const float* cond    = (const float*)d_in[3];

    cudaFuncSetAttribute(gnn_fused, cudaFuncAttributeMaxDynamicSharedMemorySize,
                         SMEM_BYTES);

    gnn_fused<<<513, NTHREADS, SMEM_BYTES>>>(
        edges, nodes, nparams,
        (const float*)d_in[4],  (const float*)d_in[5],
        (const float*)d_in[6],  (const float*)d_in[7],
        (const float*)d_in[8],  (const float*)d_in[9],
        (const float*)d_in[10], (const float*)d_in[11],
        (const float*)d_in[12], (const float*)d_in[13],
        (const float*)d_in[14], (const float*)d_in[15],
        (const float*)d_in[16], (const float*)d_in[17],
        (const float*)d_in[18], (const float*)d_in[19],
        (const float*)d_in[20], (const float*)d_in[21],
        (const float*)d_in[22], (const float*)d_in[23],
        (const float*)d_in[24], (const float*)d_in[25],
        (const float*)d_in[26], (const float*)d_in[27]);

    gnn_final<<<1, 512>>>(cond, (float*)d_out);
}